// round 16
// baseline (speedup 1.0000x reference)
#include <cuda_runtime.h>
#include <cuda_bf16.h>
#include <cstdint>

typedef unsigned int u32; typedef unsigned long long u64; typedef unsigned short u16;

// ---------------- scratch (__device__ globals; no runtime allocation) --------
__device__ float g_qp[32 * 1024];
__device__ float g_spart[16 * 65536];            // partials [wn*4+hc][row]
__device__ float g_ctx_part[16 * 32 * 1024];
__device__ u32 g_mt_flag[512];                   // per-mtile ready count (target 64)
__device__ u32 g_w1_cnt;                         // W1 convert barrier (target 148)
// tiled + pre-swizzled: A blocks [mtile(512)][kt(32)] of 8KB (128 rows x 64B)
__device__ __align__(16) u16 g_vh[67108864];
__device__ __align__(16) u16 g_vl[67108864];
// tiled + pre-swizzled: B blocks [hc(4)][kt(32)] of 16KB (256 rows x 64B)
__device__ __align__(16) u16 g_w1t_h[1048576];
__device__ __align__(16) u16 g_w1t_l[1048576];

// ---------------- helpers ----------------------------------------------------
__device__ __forceinline__ u32 smem_u32(const void* p) {
    u32 a;
    asm("{ .reg .u64 t; cvta.to.shared.u64 t, %1; cvt.u32.u64 %0, t; }" : "=r"(a) : "l"(p));
    return a;
}
#define MBAR_INIT(a, c) asm volatile("mbarrier.init.shared.b64 [%0], %1;" :: "r"((u32)(a)), "r"((u32)(c)) : "memory")
#define MBAR_ARRIVE(a)  asm volatile("mbarrier.arrive.shared.b64 _, [%0];" :: "r"((u32)(a)) : "memory")
#define MBAR_EXPECT_TX(a, tx) asm volatile("mbarrier.arrive.expect_tx.shared.b64 _, [%0], %1;" :: "r"((u32)(a)), "r"((u32)(tx)) : "memory")
#define MBAR_WAIT(a, par) do {                                                   \
    u32 _m = (u32)(a); u32 _p = (u32)(par); u32 _d;                              \
    asm volatile("{\n\t.reg .pred p;\n\t"                                        \
        "mbarrier.try_wait.parity.acquire.cta.shared::cta.b64 p, [%1], %2;\n\t"  \
        "selp.b32 %0, 1, 0, p;\n\t}" : "=r"(_d) : "r"(_m), "r"(_p) : "memory");  \
    if (!_d) {                                                                   \
        asm volatile("{\n\t.reg .pred P1;\n\t"                                   \
            "WL_%=:\n\t"                                                         \
            "mbarrier.try_wait.parity.acquire.cta.shared::cta.b64 P1, [%0], %1, 0x989680;\n\t" \
            "@P1 bra.uni WD_%=;\n\tbra.uni WL_%=;\n\tWD_%=:\n\t}"                \
            :: "r"(_m), "r"(_p) : "memory");                                     \
    } } while (0)
#define BULK_G2S(dst, src, sz, mb) \
    asm volatile("cp.async.bulk.shared::cta.global.mbarrier::complete_tx::bytes [%0], [%1], %2, [%3];" \
                 :: "r"((u32)(dst)), "l"(src), "r"((u32)(sz)), "r"((u32)(mb)) : "memory")

__device__ __forceinline__ u32 ld_acq(const u32* p) {
    u32 v;
    asm volatile("ld.acquire.gpu.u32 %0, [%1];" : "=r"(v) : "l"(p) : "memory");
    return v;
}
__device__ __forceinline__ void spin_flag(const u32* p, u32 target) {
    while (ld_acq(p) < target) { }
}

__device__ __forceinline__ void ldsm4(u32 (&r)[4], u32 addr) {
    asm volatile("ldmatrix.sync.aligned.m8n8.x4.shared.b16 {%0,%1,%2,%3}, [%4];"
                 : "=r"(r[0]), "=r"(r[1]), "=r"(r[2]), "=r"(r[3]) : "r"(addr));
}
__device__ __forceinline__ void mma16816(float* c, const u32* a, const u32* b) {
    asm volatile(
        "mma.sync.aligned.m16n8k16.row.col.f32.bf16.bf16.f32 "
        "{%0,%1,%2,%3}, {%4,%5,%6,%7}, {%8,%9}, {%0,%1,%2,%3};"
        : "+f"(c[0]), "+f"(c[1]), "+f"(c[2]), "+f"(c[3])
        : "r"(a[0]), "r"(a[1]), "r"(a[2]), "r"(a[3]), "r"(b[0]), "r"(b[1]));
}

__device__ __forceinline__ u16 f2bf(float x) { return __bfloat16_as_ushort(__float2bfloat16_rn(x)); }
__device__ __forceinline__ float bf2f(u16 u) { return __bfloat162float(__ushort_as_bfloat16(u)); }
__device__ __forceinline__ float tanh_fast(float x) {
    float e = __expf(2.0f * x);
    return 1.0f - __fdividef(2.0f, e + 1.0f);
}

// convert one float4 of values into swizzled hi/lo uint2
__device__ __forceinline__ void conv_store_f4(const float4& x, u32 mt, u32 r_loc, u32 c4) {
    u16 h0 = f2bf(x.x), h1 = f2bf(x.y), h2 = f2bf(x.z), h3 = f2bf(x.w);
    u16 l0 = f2bf(x.x - bf2f(h0)), l1 = f2bf(x.y - bf2f(h1));
    u16 l2 = f2bf(x.z - bf2f(h2)), l3 = f2bf(x.w - bf2f(h3));
    const u32 kt = c4 >> 3;
    const u32 c = (c4 & 7) >> 1;
    const u32 swz = c ^ ((r_loc >> 1) & 3);
    const size_t off = (size_t)(mt * 32 + kt) * 8192 + r_loc * 64 + swz * 16 + (c4 & 1) * 8;
    *(uint2*)((char*)g_vh + off) = make_uint2((u32)h0 | ((u32)h1 << 16), (u32)h2 | ((u32)h3 << 16));
    *(uint2*)((char*)g_vl + off) = make_uint2((u32)l0 | ((u32)l1 << 16), (u32)l2 | ((u32)l3 << 16));
}

// ---------------- K0: zero ready-flags (runs first every launch) -------------
__global__ void zero_flags_kernel() {
    u32 t = threadIdx.x;
    if (t < 512) g_mt_flag[t] = 0;
    if (t == 512) g_w1_cnt = 0;
}

// ---------------- K1: query_proj = query @ W2 --------------------------------
__global__ void qp_kernel(const float* __restrict__ query, const float* __restrict__ W2) {
    __shared__ float sq[1024];
    int hc = blockIdx.x, b = blockIdx.y;
    for (int i = threadIdx.x; i < 1024; i += 256) sq[i] = query[b * 1024 + i];
    __syncthreads();
    int h = hc * 256 + threadIdx.x;
    float acc = 0.f;
#pragma unroll 8
    for (int d = 0; d < 1024; d++) acc += sq[d] * W2[(size_t)d * 1024 + h];
    g_qp[b * 1024 + h] = acc;
}

// ---------------- K3: persistent scores + fused conversion -------------------
// 2048 units = 512 M-tiles x 4 H-chunks (hc = bx & 3, constant per CTA).
// Unit: M=128, N=256, K=1024, 16 stages of Kc=64. 148 CTAs x 512 thr.
// W1 converted up-front (all CTAs, gpu barrier); values converted JIT:
// round r (mtile (bx>>2)+37r) converted by its 4-CTA group during unit r-1
// stages 0..7 (4 rows/stage/CTA), flag target 64 = 4 CTA x 16 warps.
#define AH_OFF   0
#define AL_OFF   16384
#define BH_OFF   32768
#define BL_OFF   65536
#define STAGE_B  98304
#define DYN_BYTES (2 * STAGE_B)    // 196608
#define NCTA     148
#define NUNITS   2048

__global__ __launch_bounds__(512, 1)
void scores_mma(const float* __restrict__ vvec,
                const float* __restrict__ values,
                const float* __restrict__ W1) {
    extern __shared__ __align__(16) char dyn[];
    const u32 dynb = smem_u32(dyn);

    __shared__ __align__(8) u64 s_full[2], s_empty[2];

    const int tid = threadIdx.x;
    const int lane = tid & 31;
    const int wid = tid >> 5;
    const int wm = wid & 3;          // 4 m-warps (32 rows each)
    const int wn = wid >> 2;         // 4 n-warps (64 cols each)
    const int bx = blockIdx.x;
    const int hc = bx & 3;           // constant per CTA (148 % 4 == 0)
    const u32 grp = (u32)(bx >> 2);  // mtile group 0..36
    const u32 quarter = (u32)(bx & 3) * 32u;
    const u32 full0 = smem_u32(&s_full[0]);
    const u32 empty0 = smem_u32(&s_empty[0]);

    // fragment address maps (identical in-block layout to R15)
    const u32 rA0 = (u32)(wm * 32 + (lane & 15));
    const u32 keyA = (rA0 >> 1) & 3;
    u32 a_base[2], aswz[2];
#pragma unroll
    for (int tm = 0; tm < 2; tm++) a_base[tm] = (rA0 + (u32)tm * 16u) * 64u;
#pragma unroll
    for (int k2 = 0; k2 < 2; k2++)
        aswz[k2] = (((u32)(lane >> 4) | ((u32)k2 << 1)) ^ keyA) << 4;

    const u32 rB0 = (u32)(wn * 64 + ((lane >> 4) << 3) + (lane & 7));
    const u32 keyB = (rB0 >> 1) & 3;
    u32 b_base[2][2], bswz[2];
#pragma unroll
    for (int nh = 0; nh < 2; nh++)
#pragma unroll
        for (int p = 0; p < 2; p++)
            b_base[nh][p] = (rB0 + (u32)(nh * 32 + p * 16)) * 64u;
#pragma unroll
    for (int k2 = 0; k2 < 2; k2++)
        bswz[k2] = (((u32)((lane >> 3) & 1) | ((u32)k2 << 1)) ^ keyB) << 4;

    const int nunits = (NUNITS - bx + NCTA - 1) / NCTA;
    const int total = nunits * 16;   // 16 Kc=64 stages per unit

    if (tid == 0) {
#pragma unroll
        for (int s = 0; s < 2; s++) { MBAR_INIT(full0 + s * 8, 1); MBAR_INIT(empty0 + s * 8, 16); }
    }

    // ---- convert W1 slice (all threads; linear read, swizzled write) --------
    for (u32 i = (u32)bx * 512u + (u32)tid; i < 1048576u; i += 75776u) {
        float x = W1[i];
        u16 hi = f2bf(x);
        u16 lo = f2bf(x - bf2f(hi));
        const u32 h = i & 1023u, d = i >> 10;
        const u32 hcid = h >> 8, rr = h & 255u;
        const u32 kt = d >> 5, c = (d & 31u) >> 3;
        const u32 swz = c ^ ((rr >> 1) & 3u);
        const size_t off = (size_t)(hcid * 32 + kt) * 16384 + rr * 64 + swz * 16 + (d & 7u) * 2;
        *(u16*)((char*)g_w1t_h + off) = hi;
        *(u16*)((char*)g_w1t_l + off) = lo;
    }
    __syncthreads();
    if (tid == 0) { __threadfence(); atomicAdd(&g_w1_cnt, 1u); }

    // ---- convert round 0 (mtile grp, this CTA's 32-row quarter) -------------
    {
        const u32 mt0 = grp;
#pragma unroll
        for (int j = 0; j < 16; j++) {
            const u32 idx = (u32)tid + (u32)j * 512u;      // 8192 f4
            const u32 row_in = idx >> 8;                    // 0..31
            const u32 c4 = idx & 255u;
            const u32 grow = mt0 * 128u + quarter + row_in;
            float4 x = *(const float4*)(values + (size_t)grow * 1024 + c4 * 4);
            conv_store_f4(x, mt0, grow & 127u, c4);
        }
    }
    __syncthreads();
    if (lane == 0) { __threadfence(); atomicAdd(&g_mt_flag[grp], 1u); }   // 16 per CTA

    // ---- prologue: producer fills both buffers (needs W1 + round 0) ---------
    if (tid == 0) {
        spin_flag(&g_w1_cnt, NCTA);
        spin_flag(&g_mt_flag[grp], 64u);
#pragma unroll
        for (int g = 0; g < 2; g++) {
            const u32 mt = grp, kt = (u32)g * 2u;
            const u32 base = dynb + (u32)g * STAGE_B;
            const u32 mb = full0 + (u32)g * 8;
            MBAR_EXPECT_TX(mb, STAGE_B);
            BULK_G2S(base + AH_OFF, (const char*)g_vh + (size_t)(mt * 32 + kt) * 8192, 16384, mb);
            BULK_G2S(base + AL_OFF, (const char*)g_vl + (size_t)(mt * 32 + kt) * 8192, 16384, mb);
            BULK_G2S(base + BH_OFF, (const char*)g_w1t_h + (size_t)((u32)hc * 32 + kt) * 16384, 32768, mb);
            BULK_G2S(base + BL_OFF, (const char*)g_w1t_l + (size_t)((u32)hc * 32 + kt) * 16384, 32768, mb);
        }
    }
    __syncthreads();   // all warps see initialized mbarriers before waiting

    float acc[2][8][4];
#pragma unroll
    for (int tm = 0; tm < 2; tm++)
#pragma unroll
        for (int tn = 0; tn < 8; tn++)
#pragma unroll
            for (int q = 0; q < 4; q++) acc[tm][tn][q] = 0.f;

    for (int ls = 0; ls < total; ls++) {
        const u32 sb = (u32)(ls & 1);
        const u32 ph = (u32)((ls >> 1) & 1);
        MBAR_WAIT(full0 + sb * 8, ph);
        const u32 base = dynb + sb * STAGE_B;
#pragma unroll
        for (int kk = 0; kk < 4; kk++) {
            const u32 subA = (u32)(kk >> 1) * 8192u;
            const u32 subB = (u32)(kk >> 1) * 16384u;
            const int k2 = kk & 1;
            u32 ah[2][4], al[2][4];
#pragma unroll
            for (int tm = 0; tm < 2; tm++) {
                ldsm4(ah[tm], base + AH_OFF + subA + a_base[tm] + aswz[k2]);
                ldsm4(al[tm], base + AL_OFF + subA + a_base[tm] + aswz[k2]);
            }
#pragma unroll
            for (int nh = 0; nh < 2; nh++) {
                u32 bh[2][4], bl[2][4];
#pragma unroll
                for (int p = 0; p < 2; p++) {
                    ldsm4(bh[p], base + BH_OFF + subB + b_base[nh][p] + bswz[k2]);
                    ldsm4(bl[p], base + BL_OFF + subB + b_base[nh][p] + bswz[k2]);
                }
                // hoisted arrive: after the stage's FINAL ldsm, before its mma
                if (kk == 3 && nh == 1 && lane == 0) MBAR_ARRIVE(empty0 + sb * 8);
#pragma unroll
                for (int p = 0; p < 2; p++)
#pragma unroll
                    for (int q = 0; q < 2; q++) {
                        const int tn = nh * 4 + p * 2 + q;
#pragma unroll
                        for (int tm = 0; tm < 2; tm++) {
                            mma16816(acc[tm][tn], ah[tm], &bh[p][q * 2]);
                            mma16816(acc[tm][tn], al[tm], &bh[p][q * 2]);
                            mma16816(acc[tm][tn], ah[tm], &bl[p][q * 2]);
                        }
                    }
            }
        }

        // ---- JIT conversion: round (unit+1), 4 rows per stage s=0..7 --------
        {
            const int s = ls & 15;
            const int r = (ls >> 4) + 1;
            if (s < 8 && r < nunits) {
                const u32 mt = grp + 37u * (u32)r;
                const u32 idx = (u32)tid * 2u;
                const u32 row_in = (u32)(tid >> 7);         // 0..3
                const u32 c4 = idx & 255u;
                const u32 grow = mt * 128u + quarter + (u32)s * 4u + row_in;
                const float* src = values + (size_t)grow * 1024 + c4 * 4;
                float4 x0 = *(const float4*)src;
                float4 x1 = *(const float4*)(src + 4);
                const u32 rl = grow & 127u;
                conv_store_f4(x0, mt, rl, c4);
                conv_store_f4(x1, mt, rl, c4 + 1u);
                if (s == 7 && lane == 0) { __threadfence(); atomicAdd(&g_mt_flag[mt], 1u); }
            }
        }

        // producer (inline, warp 15): refill buffer sb with stage ls+2
        if (wid == 15 && lane == 0) {
            const int g = ls + 2;
            if (g < total) {
                MBAR_WAIT(empty0 + sb * 8, ph);
                const u32 mt = grp + 37u * (u32)(g >> 4);
                const u32 kt = (u32)(g & 15) * 2u;
                spin_flag(&g_mt_flag[mt], 64u);
                const u32 mb = full0 + sb * 8;
                MBAR_EXPECT_TX(mb, STAGE_B);
                BULK_G2S(base + AH_OFF, (const char*)g_vh + (size_t)(mt * 32 + kt) * 8192, 16384, mb);
                BULK_G2S(base + AL_OFF, (const char*)g_vl + (size_t)(mt * 32 + kt) * 8192, 16384, mb);
                BULK_G2S(base + BH_OFF, (const char*)g_w1t_h + (size_t)((u32)hc * 32 + kt) * 16384, 32768, mb);
                BULK_G2S(base + BL_OFF, (const char*)g_w1t_l + (size_t)((u32)hc * 32 + kt) * 16384, 32768, mb);
            }
        }

        if ((ls & 15) == 15) {               // unit complete -> barrier-free epilogue
            const int u = bx + (ls >> 4) * NCTA;
            const u32 m0 = (u32)(u >> 2) * 128u;
            const int b = (int)(m0 >> 11);
            const float* qpp = g_qp + b * 1024 + hc * 256;
            const float* vvp = vvec + hc * 256;

            float srow[4] = {0.f, 0.f, 0.f, 0.f};
#pragma unroll
            for (int tn = 0; tn < 8; tn++) {
                const int c0 = wn * 64 + tn * 8 + (lane & 3) * 2;
                const float q0 = qpp[c0], q1 = qpp[c0 + 1];
                const float v0 = vvp[c0], v1 = vvp[c0 + 1];
#pragma unroll
                for (int tm = 0; tm < 2; tm++) {
                    srow[tm * 2 + 0] += tanh_fast(acc[tm][tn][0] + q0) * v0 +
                                        tanh_fast(acc[tm][tn][1] + q1) * v1;
                    srow[tm * 2 + 1] += tanh_fast(acc[tm][tn][2] + q0) * v0 +
                                        tanh_fast(acc[tm][tn][3] + q1) * v1;
                    acc[tm][tn][0] = 0.f; acc[tm][tn][1] = 0.f;
                    acc[tm][tn][2] = 0.f; acc[tm][tn][3] = 0.f;
                }
            }
#pragma unroll
            for (int i = 0; i < 4; i++) {
                srow[i] += __shfl_xor_sync(0xffffffffu, srow[i], 1);
                srow[i] += __shfl_xor_sync(0xffffffffu, srow[i], 2);
            }
            if ((lane & 3) == 0) {
                float* sp = g_spart + (size_t)(wn * 4 + hc) * 65536 + m0;
                const int r0 = wm * 32 + (lane >> 2);
                sp[r0]      = srow[0];
                sp[r0 + 8]  = srow[1];
                sp[r0 + 16] = srow[2];
                sp[r0 + 24] = srow[3];
            }
        }
    }
}

// ---------------- K4: softmax over S (sums 16 partials) ----------------------
__global__ void softmax_kernel(float* __restrict__ w) {
    int b = blockIdx.x;
    float* p = w + b * 2048;
    int t = threadIdx.x;
    __shared__ float sm[32];
    const int r0 = b * 2048 + t;
    float a0 = 0.f, a1 = 0.f;
#pragma unroll
    for (int j = 0; j < 16; j++) {
        a0 += g_spart[(size_t)j * 65536 + r0];
        a1 += g_spart[(size_t)j * 65536 + r0 + 1024];
    }
    float m = fmaxf(a0, a1);
#pragma unroll
    for (int o = 16; o; o >>= 1) m = fmaxf(m, __shfl_xor_sync(0xffffffffu, m, o));
    if ((t & 31) == 0) sm[t >> 5] = m;
    __syncthreads();
    if (t < 32) {
        float mm = sm[t];
#pragma unroll
        for (int o = 16; o; o >>= 1) mm = fmaxf(mm, __shfl_xor_sync(0xffffffffu, mm, o));
        sm[t] = mm;
    }
    __syncthreads();
    m = sm[0];
    __syncthreads();
    float e0 = __expf(a0 - m), e1 = __expf(a1 - m);
    float s = e0 + e1;
#pragma unroll
    for (int o = 16; o; o >>= 1) s += __shfl_xor_sync(0xffffffffu, s, o);
    if ((t & 31) == 0) sm[t >> 5] = s;
    __syncthreads();
    if (t < 32) {
        float ss = sm[t];
#pragma unroll
        for (int o = 16; o; o >>= 1) ss += __shfl_xor_sync(0xffffffffu, ss, o);
        sm[t] = ss;
    }
    __syncthreads();
    float inv = 1.0f / sm[0];
    p[t] = e0 * inv;
    p[t + 1024] = e1 * inv;
}

// ---------------- K5/K6: context = w @ values --------------------------------
__global__ void ctx_part_kernel(const float* __restrict__ values, const float* __restrict__ w) {
    int b = blockIdx.x, j = blockIdx.y;
    __shared__ float ws[128];
    int t = threadIdx.x;
    if (t < 128) ws[t] = w[b * 2048 + j * 128 + t];
    __syncthreads();
    const float* V = values + ((size_t)(b * 2048 + j * 128)) * 1024 + t * 4;
    float4 acc = make_float4(0.f, 0.f, 0.f, 0.f);
#pragma unroll 8
    for (int s = 0; s < 128; s++) {
        float4 x = *(const float4*)(V + (size_t)s * 1024);
        float c = ws[s];
        acc.x += c * x.x; acc.y += c * x.y; acc.z += c * x.z; acc.w += c * x.w;
    }
    *(float4*)&g_ctx_part[((size_t)j * 32 + b) * 1024 + t * 4] = acc;
}

__global__ void ctx_reduce_kernel(float* __restrict__ ctx) {
    int b = blockIdx.x, t = threadIdx.x;
    float4 acc = make_float4(0.f, 0.f, 0.f, 0.f);
#pragma unroll
    for (int j = 0; j < 16; j++) {
        float4 x = *(const float4*)&g_ctx_part[((size_t)j * 32 + b) * 1024 + t * 4];
        acc.x += x.x; acc.y += x.y; acc.z += x.z; acc.w += x.w;
    }
    *(float4*)(ctx + b * 1024 + t * 4) = acc;
}

// ---------------- launch ------------------------------------------------------
extern "C" void kernel_launch(void* const* d_in, const int* in_sizes, int n_in,
                              void* d_out, int out_size) {
    const float* query  = (const float*)d_in[0];
    const float* values = (const float*)d_in[1];
    const float* W1     = (const float*)d_in[2];
    const float* W2     = (const float*)d_in[3];
    const float* v      = (const float*)d_in[4];

    float* ctx     = (float*)d_out;
    float* weights = (float*)d_out + 32 * 1024;

    cudaFuncSetAttribute(scores_mma, cudaFuncAttributeMaxDynamicSharedMemorySize, DYN_BYTES);

    zero_flags_kernel<<<1, 544>>>();
    qp_kernel<<<dim3(4, 32), 256>>>(query, W2);
    scores_mma<<<NCTA, 512, DYN_BYTES>>>(v, values, W1);
    softmax_kernel<<<32, 1024>>>(weights);
    ctx_part_kernel<<<dim3(32, 16), 256>>>(values, weights);
    ctx_reduce_kernel<<<32, 256>>>(ctx);
}

// round 17
// speedup vs baseline: 1.0866x; 1.0866x over previous
#include <cuda_runtime.h>
#include <cuda_bf16.h>
#include <cstdint>

typedef unsigned int u32; typedef unsigned long long u64; typedef unsigned short u16;

// ---------------- scratch (__device__ globals; no runtime allocation) --------
__device__ float g_qp[32 * 1024];
__device__ float g_spart[16 * 65536];            // partials [wn*4+hc][row]
__device__ float g_ctx_part[16 * 32 * 1024];
// tiled + pre-swizzled: A blocks [mtile(512)][kt(32)] of 8KB (128 rows x 64B)
__device__ __align__(16) u16 g_vh[67108864];
__device__ __align__(16) u16 g_vl[67108864];
// tiled + pre-swizzled: B blocks [hc(4)][kt(32)] of 16KB (256 rows x 64B)
__device__ __align__(16) u16 g_w1t_h[1048576];
__device__ __align__(16) u16 g_w1t_l[1048576];

// ---------------- helpers ----------------------------------------------------
__device__ __forceinline__ u32 smem_u32(const void* p) {
    u32 a;
    asm("{ .reg .u64 t; cvta.to.shared.u64 t, %1; cvt.u32.u64 %0, t; }" : "=r"(a) : "l"(p));
    return a;
}
#define MBAR_INIT(a, c) asm volatile("mbarrier.init.shared.b64 [%0], %1;" :: "r"((u32)(a)), "r"((u32)(c)) : "memory")
#define MBAR_ARRIVE(a)  asm volatile("mbarrier.arrive.shared.b64 _, [%0];" :: "r"((u32)(a)) : "memory")
#define MBAR_EXPECT_TX(a, tx) asm volatile("mbarrier.arrive.expect_tx.shared.b64 _, [%0], %1;" :: "r"((u32)(a)), "r"((u32)(tx)) : "memory")
#define MBAR_WAIT(a, par) do {                                                   \
    u32 _m = (u32)(a); u32 _p = (u32)(par); u32 _d;                              \
    asm volatile("{\n\t.reg .pred p;\n\t"                                        \
        "mbarrier.try_wait.parity.acquire.cta.shared::cta.b64 p, [%1], %2;\n\t"  \
        "selp.b32 %0, 1, 0, p;\n\t}" : "=r"(_d) : "r"(_m), "r"(_p) : "memory");  \
    if (!_d) {                                                                   \
        asm volatile("{\n\t.reg .pred P1;\n\t"                                   \
            "WL_%=:\n\t"                                                         \
            "mbarrier.try_wait.parity.acquire.cta.shared::cta.b64 P1, [%0], %1, 0x989680;\n\t" \
            "@P1 bra.uni WD_%=;\n\tbra.uni WL_%=;\n\tWD_%=:\n\t}"                \
            :: "r"(_m), "r"(_p) : "memory");                                     \
    } } while (0)
#define BULK_G2S(dst, src, sz, mb) \
    asm volatile("cp.async.bulk.shared::cta.global.mbarrier::complete_tx::bytes [%0], [%1], %2, [%3];" \
                 :: "r"((u32)(dst)), "l"(src), "r"((u32)(sz)), "r"((u32)(mb)) : "memory")

__device__ __forceinline__ void ldsm4(u32 (&r)[4], u32 addr) {
    asm volatile("ldmatrix.sync.aligned.m8n8.x4.shared.b16 {%0,%1,%2,%3}, [%4];"
                 : "=r"(r[0]), "=r"(r[1]), "=r"(r[2]), "=r"(r[3]) : "r"(addr));
}
__device__ __forceinline__ void mma16816(float* c, const u32* a, const u32* b) {
    asm volatile(
        "mma.sync.aligned.m16n8k16.row.col.f32.bf16.bf16.f32 "
        "{%0,%1,%2,%3}, {%4,%5,%6,%7}, {%8,%9}, {%0,%1,%2,%3};"
        : "+f"(c[0]), "+f"(c[1]), "+f"(c[2]), "+f"(c[3])
        : "r"(a[0]), "r"(a[1]), "r"(a[2]), "r"(a[3]), "r"(b[0]), "r"(b[1]));
}

__device__ __forceinline__ u16 f2bf(float x) { return __bfloat16_as_ushort(__float2bfloat16_rn(x)); }
__device__ __forceinline__ float bf2f(u16 u) { return __bfloat162float(__ushort_as_bfloat16(u)); }
__device__ __forceinline__ float tanh_fast(float x) {
    float e = __expf(2.0f * x);
    return 1.0f - __fdividef(2.0f, e + 1.0f);
}

// ---------------- K1: query_proj = query @ W2 (W2 read once per block) -------
// grid (16 h-chunks of 64, 8 b-quads), 256 thr: hx = t&63, ty = t>>6 splits D
// into quarters. Per-block W2 slice read once -> 32 MB total. smem reduce.
__global__ void qp_kernel(const float* __restrict__ query, const float* __restrict__ W2) {
    __shared__ float sq[4][1024];
    __shared__ float red[4][64][4];
    const int t = threadIdx.x;
    const int hx = t & 63, ty = t >> 6;
    const int h = blockIdx.x * 64 + hx;
    const int b0 = blockIdx.y * 4;
    for (int i = t; i < 4096; i += 256)
        sq[i >> 10][i & 1023] = query[(b0 + (i >> 10)) * 1024 + (i & 1023)];
    __syncthreads();
    float acc0 = 0.f, acc1 = 0.f, acc2 = 0.f, acc3 = 0.f;
    const int d0 = ty * 256;
#pragma unroll 4
    for (int dd = 0; dd < 256; dd++) {
        const int d = d0 + dd;
        const float w = W2[(size_t)d * 1024 + h];
        acc0 += sq[0][d] * w; acc1 += sq[1][d] * w;
        acc2 += sq[2][d] * w; acc3 += sq[3][d] * w;
    }
    red[ty][hx][0] = acc0; red[ty][hx][1] = acc1;
    red[ty][hx][2] = acc2; red[ty][hx][3] = acc3;
    __syncthreads();
    if (ty == 0) {
#pragma unroll
        for (int i = 0; i < 4; i++) {
            float s = (red[0][hx][i] + red[1][hx][i]) + (red[2][hx][i] + red[3][hx][i]);
            g_qp[(b0 + i) * 1024 + h] = s;
        }
    }
}

// ---------------- K2: converts into tiled, pre-swizzled layout ---------------
__global__ void conv_values_kernel(const float* __restrict__ src) {
    u32 i = blockIdx.x * 256u + threadIdx.x;     // one float4
    float4 x = ((const float4*)src)[i];
    u16 h0 = f2bf(x.x), h1 = f2bf(x.y), h2 = f2bf(x.z), h3 = f2bf(x.w);
    u16 l0 = f2bf(x.x - bf2f(h0)), l1 = f2bf(x.y - bf2f(h1));
    u16 l2 = f2bf(x.z - bf2f(h2)), l3 = f2bf(x.w - bf2f(h3));
    const u32 m = i >> 8;                 // global row
    const u32 k = (i & 255) * 4;          // col
    const u32 mt = m >> 7, r = m & 127;
    const u32 kt = k >> 5, c = (k & 31) >> 3;
    const u32 swz = c ^ ((r >> 1) & 3);
    const size_t off = (size_t)(mt * 32 + kt) * 8192 + r * 64 + swz * 16 + (k & 7) * 2;
    *(uint2*)((char*)g_vh + off) = make_uint2((u32)h0 | ((u32)h1 << 16), (u32)h2 | ((u32)h3 << 16));
    *(uint2*)((char*)g_vl + off) = make_uint2((u32)l0 | ((u32)l1 << 16), (u32)l2 | ((u32)l3 << 16));
}

__global__ void conv_w1_kernel(const float* __restrict__ W1) {
    __shared__ float t[32][33];
    int d0 = blockIdx.x * 32, h0 = blockIdx.y * 32;
    int tx = threadIdx.x, ty = threadIdx.y;  // 32 x 8
#pragma unroll
    for (int i = 0; i < 4; i++) {
        int d = ty * 4 + i;
        t[d][tx] = W1[(size_t)(d0 + d) * 1024 + h0 + tx];
    }
    __syncthreads();
#pragma unroll
    for (int i = 0; i < 4; i++) {
        int h = h0 + ty * 4 + i;
        int d = d0 + tx;
        float x = t[tx][(h - h0)];
        u16 hi = f2bf(x);
        u16 lo = f2bf(x - bf2f(hi));
        const u32 hcid = (u32)h >> 8, r = (u32)h & 255;
        const u32 kt = (u32)d >> 5, c = ((u32)d & 31) >> 3;
        const u32 swz = c ^ ((r >> 1) & 3);
        const size_t off = (size_t)(hcid * 32 + kt) * 16384 + r * 64 + swz * 16 + ((u32)d & 7) * 2;
        *(u16*)((char*)g_w1t_h + off) = hi;
        *(u16*)((char*)g_w1t_l + off) = lo;
    }
}

// ---------------- K3: persistent scores, Kc=64 double-buffer (R15) -----------
#define AH_OFF   0
#define AL_OFF   16384
#define BH_OFF   32768
#define BL_OFF   65536
#define STAGE_B  98304
#define DYN_BYTES (2 * STAGE_B)    // 196608
#define NCTA     148
#define NUNITS   2048

__global__ __launch_bounds__(512, 1)
void scores_mma(const float* __restrict__ vvec) {
    extern __shared__ __align__(16) char dyn[];
    const u32 dynb = smem_u32(dyn);

    __shared__ __align__(8) u64 s_full[2], s_empty[2];

    const int tid = threadIdx.x;
    const int lane = tid & 31;
    const int wid = tid >> 5;
    const int wm = wid & 3;          // 4 m-warps (32 rows each)
    const int wn = wid >> 2;         // 4 n-warps (64 cols each)
    const int bx = blockIdx.x;
    const int hc = bx & 3;           // constant per CTA (148 % 4 == 0)
    const u32 full0 = smem_u32(&s_full[0]);
    const u32 empty0 = smem_u32(&s_empty[0]);

    const u32 rA0 = (u32)(wm * 32 + (lane & 15));
    const u32 keyA = (rA0 >> 1) & 3;
    u32 a_base[2], aswz[2];
#pragma unroll
    for (int tm = 0; tm < 2; tm++) a_base[tm] = (rA0 + (u32)tm * 16u) * 64u;
#pragma unroll
    for (int k2 = 0; k2 < 2; k2++)
        aswz[k2] = (((u32)(lane >> 4) | ((u32)k2 << 1)) ^ keyA) << 4;

    const u32 rB0 = (u32)(wn * 64 + ((lane >> 4) << 3) + (lane & 7));
    const u32 keyB = (rB0 >> 1) & 3;
    u32 b_base[2][2], bswz[2];
#pragma unroll
    for (int nh = 0; nh < 2; nh++)
#pragma unroll
        for (int p = 0; p < 2; p++)
            b_base[nh][p] = (rB0 + (u32)(nh * 32 + p * 16)) * 64u;
#pragma unroll
    for (int k2 = 0; k2 < 2; k2++)
        bswz[k2] = (((u32)((lane >> 3) & 1) | ((u32)k2 << 1)) ^ keyB) << 4;

    const int nunits = (NUNITS - bx + NCTA - 1) / NCTA;
    const int total = nunits * 16;   // 16 Kc=64 stages per unit

    if (tid == 0) {
#pragma unroll
        for (int s = 0; s < 2; s++) { MBAR_INIT(full0 + s * 8, 1); MBAR_INIT(empty0 + s * 8, 16); }
    }
    __syncthreads();

    if (tid == 0) {
#pragma unroll
        for (int g = 0; g < 2; g++) {
            const u32 mt = (u32)(bx >> 2), kt = (u32)g * 2u;
            const u32 base = dynb + (u32)g * STAGE_B;
            const u32 mb = full0 + (u32)g * 8;
            MBAR_EXPECT_TX(mb, STAGE_B);
            BULK_G2S(base + AH_OFF, (const char*)g_vh + (size_t)(mt * 32 + kt) * 8192, 16384, mb);
            BULK_G2S(base + AL_OFF, (const char*)g_vl + (size_t)(mt * 32 + kt) * 8192, 16384, mb);
            BULK_G2S(base + BH_OFF, (const char*)g_w1t_h + (size_t)((u32)hc * 32 + kt) * 16384, 32768, mb);
            BULK_G2S(base + BL_OFF, (const char*)g_w1t_l + (size_t)((u32)hc * 32 + kt) * 16384, 32768, mb);
        }
    }

    float acc[2][8][4];
#pragma unroll
    for (int tm = 0; tm < 2; tm++)
#pragma unroll
        for (int tn = 0; tn < 8; tn++)
#pragma unroll
            for (int q = 0; q < 4; q++) acc[tm][tn][q] = 0.f;

    for (int ls = 0; ls < total; ls++) {
        const u32 sb = (u32)(ls & 1);
        const u32 ph = (u32)((ls >> 1) & 1);
        MBAR_WAIT(full0 + sb * 8, ph);
        const u32 base = dynb + sb * STAGE_B;
#pragma unroll
        for (int kk = 0; kk < 4; kk++) {
            const u32 subA = (u32)(kk >> 1) * 8192u;
            const u32 subB = (u32)(kk >> 1) * 16384u;
            const int k2 = kk & 1;
            u32 ah[2][4], al[2][4];
#pragma unroll
            for (int tm = 0; tm < 2; tm++) {
                ldsm4(ah[tm], base + AH_OFF + subA + a_base[tm] + aswz[k2]);
                ldsm4(al[tm], base + AL_OFF + subA + a_base[tm] + aswz[k2]);
            }
#pragma unroll
            for (int nh = 0; nh < 2; nh++) {
                u32 bh[2][4], bl[2][4];
#pragma unroll
                for (int p = 0; p < 2; p++) {
                    ldsm4(bh[p], base + BH_OFF + subB + b_base[nh][p] + bswz[k2]);
                    ldsm4(bl[p], base + BL_OFF + subB + b_base[nh][p] + bswz[k2]);
                }
                // hoisted arrive: after the stage's FINAL ldsm, before its mma
                if (kk == 3 && nh == 1 && lane == 0) MBAR_ARRIVE(empty0 + sb * 8);
#pragma unroll
                for (int p = 0; p < 2; p++)
#pragma unroll
                    for (int q = 0; q < 2; q++) {
                        const int tn = nh * 4 + p * 2 + q;
#pragma unroll
                        for (int tm = 0; tm < 2; tm++) {
                            mma16816(acc[tm][tn], ah[tm], &bh[p][q * 2]);
                            mma16816(acc[tm][tn], al[tm], &bh[p][q * 2]);
                            mma16816(acc[tm][tn], ah[tm], &bl[p][q * 2]);
                        }
                    }
            }
        }

        // producer (inline, warp 15): refill buffer sb with stage ls+2
        if (wid == 15 && lane == 0) {
            const int g = ls + 2;
            if (g < total) {
                MBAR_WAIT(empty0 + sb * 8, ph);
                const int u = bx + (g >> 4) * NCTA;
                const u32 mt = (u32)(u >> 2), kt = (u32)(g & 15) * 2u;
                const u32 mb = full0 + sb * 8;
                MBAR_EXPECT_TX(mb, STAGE_B);
                BULK_G2S(base + AH_OFF, (const char*)g_vh + (size_t)(mt * 32 + kt) * 8192, 16384, mb);
                BULK_G2S(base + AL_OFF, (const char*)g_vl + (size_t)(mt * 32 + kt) * 8192, 16384, mb);
                BULK_G2S(base + BH_OFF, (const char*)g_w1t_h + (size_t)((u32)hc * 32 + kt) * 16384, 32768, mb);
                BULK_G2S(base + BL_OFF, (const char*)g_w1t_l + (size_t)((u32)hc * 32 + kt) * 16384, 32768, mb);
            }
        }

        if ((ls & 15) == 15) {               // unit complete -> barrier-free epilogue
            const int u = bx + (ls >> 4) * NCTA;
            const u32 m0 = (u32)(u >> 2) * 128u;
            const int b = (int)(m0 >> 11);
            const float* qpp = g_qp + b * 1024 + hc * 256;
            const float* vvp = vvec + hc * 256;

            float srow[4] = {0.f, 0.f, 0.f, 0.f};
#pragma unroll
            for (int tn = 0; tn < 8; tn++) {
                const int c0 = wn * 64 + tn * 8 + (lane & 3) * 2;
                const float q0 = qpp[c0], q1 = qpp[c0 + 1];
                const float v0 = vvp[c0], v1 = vvp[c0 + 1];
#pragma unroll
                for (int tm = 0; tm < 2; tm++) {
                    srow[tm * 2 + 0] += tanh_fast(acc[tm][tn][0] + q0) * v0 +
                                        tanh_fast(acc[tm][tn][1] + q1) * v1;
                    srow[tm * 2 + 1] += tanh_fast(acc[tm][tn][2] + q0) * v0 +
                                        tanh_fast(acc[tm][tn][3] + q1) * v1;
                    acc[tm][tn][0] = 0.f; acc[tm][tn][1] = 0.f;
                    acc[tm][tn][2] = 0.f; acc[tm][tn][3] = 0.f;
                }
            }
#pragma unroll
            for (int i = 0; i < 4; i++) {
                srow[i] += __shfl_xor_sync(0xffffffffu, srow[i], 1);
                srow[i] += __shfl_xor_sync(0xffffffffu, srow[i], 2);
            }
            if ((lane & 3) == 0) {
                float* sp = g_spart + (size_t)(wn * 4 + hc) * 65536 + m0;
                const int r0 = wm * 32 + (lane >> 2);
                sp[r0]      = srow[0];
                sp[r0 + 8]  = srow[1];
                sp[r0 + 16] = srow[2];
                sp[r0 + 24] = srow[3];
            }
        }
    }
}

// ---------------- K4: softmax over S (sums 16 partials) ----------------------
__global__ void softmax_kernel(float* __restrict__ w) {
    int b = blockIdx.x;
    float* p = w + b * 2048;
    int t = threadIdx.x;
    __shared__ float sm[32];
    const int r0 = b * 2048 + t;
    float a0 = 0.f, a1 = 0.f;
#pragma unroll
    for (int j = 0; j < 16; j++) {
        a0 += g_spart[(size_t)j * 65536 + r0];
        a1 += g_spart[(size_t)j * 65536 + r0 + 1024];
    }
    float m = fmaxf(a0, a1);
#pragma unroll
    for (int o = 16; o; o >>= 1) m = fmaxf(m, __shfl_xor_sync(0xffffffffu, m, o));
    if ((t & 31) == 0) sm[t >> 5] = m;
    __syncthreads();
    if (t < 32) {
        float mm = sm[t];
#pragma unroll
        for (int o = 16; o; o >>= 1) mm = fmaxf(mm, __shfl_xor_sync(0xffffffffu, mm, o));
        sm[t] = mm;
    }
    __syncthreads();
    m = sm[0];
    __syncthreads();
    float e0 = __expf(a0 - m), e1 = __expf(a1 - m);
    float s = e0 + e1;
#pragma unroll
    for (int o = 16; o; o >>= 1) s += __shfl_xor_sync(0xffffffffu, s, o);
    if ((t & 31) == 0) sm[t >> 5] = s;
    __syncthreads();
    if (t < 32) {
        float ss = sm[t];
#pragma unroll
        for (int o = 16; o; o >>= 1) ss += __shfl_xor_sync(0xffffffffu, ss, o);
        sm[t] = ss;
    }
    __syncthreads();
    float inv = 1.0f / sm[0];
    p[t] = e0 * inv;
    p[t + 1024] = e1 * inv;
}

// ---------------- K5/K6: context = w @ values --------------------------------
__global__ void ctx_part_kernel(const float* __restrict__ values, const float* __restrict__ w) {
    int b = blockIdx.x, j = blockIdx.y;
    __shared__ float ws[128];
    int t = threadIdx.x;
    if (t < 128) ws[t] = w[b * 2048 + j * 128 + t];
    __syncthreads();
    const float* V = values + ((size_t)(b * 2048 + j * 128)) * 1024 + t * 4;
    float4 acc = make_float4(0.f, 0.f, 0.f, 0.f);
#pragma unroll 8
    for (int s = 0; s < 128; s++) {
        float4 x = *(const float4*)(V + (size_t)s * 1024);
        float c = ws[s];
        acc.x += c * x.x; acc.y += c * x.y; acc.z += c * x.z; acc.w += c * x.w;
    }
    *(float4*)&g_ctx_part[((size_t)j * 32 + b) * 1024 + t * 4] = acc;
}

__global__ void ctx_reduce_kernel(float* __restrict__ ctx) {
    int b = blockIdx.x, t = threadIdx.x;
    float4 acc = make_float4(0.f, 0.f, 0.f, 0.f);
#pragma unroll
    for (int j = 0; j < 16; j++) {
        float4 x = *(const float4*)&g_ctx_part[((size_t)j * 32 + b) * 1024 + t * 4];
        acc.x += x.x; acc.y += x.y; acc.z += x.z; acc.w += x.w;
    }
    *(float4*)(ctx + b * 1024 + t * 4) = acc;
}

// ---------------- launch ------------------------------------------------------
extern "C" void kernel_launch(void* const* d_in, const int* in_sizes, int n_in,
                              void* d_out, int out_size) {
    const float* query  = (const float*)d_in[0];
    const float* values = (const float*)d_in[1];
    const float* W1     = (const float*)d_in[2];
    const float* W2     = (const float*)d_in[3];
    const float* v      = (const float*)d_in[4];

    float* ctx     = (float*)d_out;
    float* weights = (float*)d_out + 32 * 1024;

    cudaFuncSetAttribute(scores_mma, cudaFuncAttributeMaxDynamicSharedMemorySize, DYN_BYTES);

    qp_kernel<<<dim3(16, 8), 256>>>(query, W2);
    conv_values_kernel<<<65536, 256>>>(values);
    conv_w1_kernel<<<dim3(32, 32), dim3(32, 8)>>>(W1);
    scores_mma<<<NCTA, 512, DYN_BYTES>>>(v);
    softmax_kernel<<<32, 1024>>>(weights);
    ctx_part_kernel<<<dim3(32, 16), 256>>>(values, weights);
    ctx_reduce_kernel<<<32, 256>>>(ctx);
}